// round 14
// baseline (speedup 1.0000x reference)
#include <cuda_runtime.h>

#define BB 8
#define CC 4
#define HH 512
#define WW 512
#define RPW 16                         // rows per warp strip
#define NSTRIPS (HH / RPW)             // 32
#define NPLANE (BB * CC)               // 32
#define NT 256
#define WPB (NT / 32)                  // 8 warps/block
#define NBLK (NPLANE * NSTRIPS * 2 / WPB)   // 256 (2 column groups of 256)
#define PD 10                          // prefetch distance (rows)

__device__ float4 g_part[NBLK];
__device__ int g_ctr = 0;

__device__ __forceinline__ float sigm(float x) {
    float t;
    asm("tanh.approx.f32 %0, %1;" : "=f"(t) : "f"(0.5f * x));
    return __fmaf_rn(0.5f, t, 0.5f);
}
__device__ __forceinline__ unsigned prmt(unsigned a, unsigned b, unsigned s) {
    unsigned r;
    asm("prmt.b32 %0, %1, %2, %3;" : "=r"(r) : "r"(a), "r"(b), "r"(s));
    return r;
}
__device__ __forceinline__ float fand(float v, unsigned m) {
    return __uint_as_float(__float_as_uint(v) & m);
}
__device__ __forceinline__ int clampr(int gr) {
    return gr < 0 ? 0 : (gr >= HH ? HH - 1 : gr);
}
__device__ __forceinline__ void pf_l2(const float* p) {
    asm volatile("prefetch.global.L2 [%0];" :: "l"(p));
}

struct Row {
    float s[8], d[8];             // horizontal sobel partials (probs), 8 columns
    unsigned sb0, sb1, db0, db1;  // packed-byte partials (targets)
};
struct Raw {
    float4 xa, xb, ta, tb;        // logits / targets (8 cols)
    float xl, xr;                 // edge-lane neighbor logits
    unsigned tl, tr;              // edge-lane neighbor targets (0/1)
};

// Pure load stage. gr MUST be in [0, HH) (caller clamps).
__device__ __forceinline__ Raw ld_raw(const float* __restrict__ lg,
                                      const float* __restrict__ tg,
                                      int gr, int c0, int lane,
                                      bool lE, bool rE)
{
    const float* rowp = lg + (size_t)gr * WW + c0;
    const float* rowt = tg + (size_t)gr * WW + c0;
    Raw r;
    r.xa = __ldg((const float4*)rowp);
    r.xb = __ldg((const float4*)(rowp + 4));
    r.ta = __ldg((const float4*)rowt);
    r.tb = __ldg((const float4*)(rowt + 4));
    r.xl = 0.f; r.xr = 0.f; r.tl = 0u; r.tr = 0u;
    if (lane == 0 && lE) {
        r.xl = __ldg(rowp - 1);
        r.tl = __float_as_uint(__ldg(rowt - 1)) >> 29;
    }
    if (lane == 31 && rE) {
        r.xr = __ldg(rowp + 8);
        r.tr = __float_as_uint(__ldg(rowt + 8)) >> 29;
    }
    return r;
}

// Process stage: MUFU + shuffles + horizontal partials (+ dice sums).
template <bool DICE>
__device__ __forceinline__ Row proc(const Raw& rw, int lane, bool lE, bool rE,
                                    float& s_pt, float& s_p, int& s_ti)
{
    float p[8];
    p[0] = sigm(rw.xa.x); p[1] = sigm(rw.xa.y); p[2] = sigm(rw.xa.z); p[3] = sigm(rw.xa.w);
    p[4] = sigm(rw.xb.x); p[5] = sigm(rw.xb.y); p[6] = sigm(rw.xb.z); p[7] = sigm(rw.xb.w);
    unsigned q1 = prmt(__float_as_uint(rw.ta.x), __float_as_uint(rw.ta.y), 0x0073u);
    unsigned q2 = prmt(__float_as_uint(rw.ta.z), __float_as_uint(rw.ta.w), 0x7300u);
    unsigned tw0 = (q1 | q2) & 0x01010101u;
    unsigned q3 = prmt(__float_as_uint(rw.tb.x), __float_as_uint(rw.tb.y), 0x0073u);
    unsigned q4 = prmt(__float_as_uint(rw.tb.z), __float_as_uint(rw.tb.w), 0x7300u);
    unsigned tw1 = (q3 | q4) & 0x01010101u;

    if (DICE) {
        s_pt = __fmaf_rn(p[0], rw.ta.x, s_pt);
        s_pt = __fmaf_rn(p[1], rw.ta.y, s_pt);
        s_pt = __fmaf_rn(p[2], rw.ta.z, s_pt);
        s_pt = __fmaf_rn(p[3], rw.ta.w, s_pt);
        s_pt = __fmaf_rn(p[4], rw.tb.x, s_pt);
        s_pt = __fmaf_rn(p[5], rw.tb.y, s_pt);
        s_pt = __fmaf_rn(p[6], rw.tb.z, s_pt);
        s_pt = __fmaf_rn(p[7], rw.tb.w, s_pt);
        s_p += ((p[0] + p[1]) + (p[2] + p[3])) + ((p[4] + p[5]) + (p[6] + p[7]));
        s_ti += __popc(tw0) + __popc(tw1);
    }

    float plin = __shfl_up_sync(0xffffffffu, p[7], 1);
    float prin = __shfl_down_sync(0xffffffffu, p[0], 1);
    unsigned twl = __shfl_up_sync(0xffffffffu, tw1, 1);
    unsigned twr = __shfl_down_sync(0xffffffffu, tw0, 1);
    float pl = plin, pr = prin;
    unsigned tli = twl >> 24, tri = twr & 0xffu;
    if (lane == 0)  { pl = lE ? sigm(rw.xl) : 0.f; tli = rw.tl; }
    if (lane == 31) { pr = rE ? sigm(rw.xr) : 0.f; tri = rw.tr; }

    Row h;
    h.s[0] = __fmaf_rn(2.f, p[0], pl + p[1]); h.d[0] = p[1] - pl;
    #pragma unroll
    for (int i = 1; i < 7; i++) {
        h.s[i] = __fmaf_rn(2.f, p[i], p[i-1] + p[i+1]);
        h.d[i] = p[i+1] - p[i-1];
    }
    h.s[7] = __fmaf_rn(2.f, p[7], p[6] + pr); h.d[7] = pr - p[6];

    unsigned wl0 = (tw0 << 8) | tli;
    unsigned wr0 = (tw0 >> 8) | ((tw1 & 0xffu) << 24);
    h.sb0 = wl0 + 2u * tw0 + wr0;
    h.db0 = (wr0 + 0x02020202u) - wl0;
    unsigned wl1 = (tw1 << 8) | (tw0 >> 24);
    unsigned wr1 = (tw1 >> 8) | (tri << 24);
    h.sb1 = wl1 + 2u * tw1 + wr1;
    h.db1 = (wr1 + 0x02020202u) - wl1;
    return h;
}

// Masked process for halo rows (raw loaded from a clamped row).
__device__ __forceinline__ Row proc_halo(const Raw& rw, int gr, int lane,
                                         bool lE, bool rE)
{
    const unsigned msk = ((unsigned)gr < (unsigned)HH) ? 0xffffffffu : 0u;
    float dpt = 0.f, dp = 0.f; int dti = 0;
    Row h = proc<false>(rw, lane, lE, rE, dpt, dp, dti);
    #pragma unroll
    for (int i = 0; i < 8; i++) { h.s[i] = fand(h.s[i], msk); h.d[i] = fand(h.d[i], msk); }
    h.sb0 &= msk; h.sb1 &= msk;
    h.db0 = (h.db0 & msk) | (0x02020202u & ~msk);
    h.db1 = (h.db1 & msk) | (0x02020202u & ~msk);
    return h;
}

__device__ __forceinline__ int combine(const Row& h0, const Row& h1, const Row& h2)
{
    bool pb[8];
    #pragma unroll
    for (int i = 0; i < 8; i++) {
        float gx = __fmaf_rn(2.f, h1.d[i], h0.d[i] + h2.d[i]);
        float gy = h2.s[i] - h0.s[i];
        pb[i] = __fmaf_rn(gx, gx, gy * gy) > 0.25f;
    }
    unsigned hx0 = h0.db0 + 2u * h1.db0 + h2.db0;
    unsigned hy0 = (h2.sb0 + 0x04040404u) - h0.sb0;
    unsigned cmb0 = (hx0 ^ 0x08080808u) | (hy0 ^ 0x04040404u);
    unsigned hx1 = h0.db1 + 2u * h1.db1 + h2.db1;
    unsigned hy1 = (h2.sb1 + 0x04040404u) - h0.sb1;
    unsigned cmb1 = (hx1 ^ 0x08080808u) | (hy1 ^ 0x04040404u);

    int m = 0;
    m += (int)(pb[0] != ((cmb0 & 0x000000FFu) != 0));
    m += (int)(pb[1] != ((cmb0 & 0x0000FF00u) != 0));
    m += (int)(pb[2] != ((cmb0 & 0x00FF0000u) != 0));
    m += (int)(pb[3] != ((cmb0 >> 24) != 0));
    m += (int)(pb[4] != ((cmb1 & 0x000000FFu) != 0));
    m += (int)(pb[5] != ((cmb1 & 0x0000FF00u) != 0));
    m += (int)(pb[6] != ((cmb1 & 0x00FF0000u) != 0));
    m += (int)(pb[7] != ((cmb1 >> 24) != 0));
    return m;
}

__global__ __launch_bounds__(NT, 2) void loss_fused(
    const float* __restrict__ logits, const float* __restrict__ targets,
    const float* __restrict__ cw, float* __restrict__ out)
{
    __shared__ float red[WPB][4];
    __shared__ float s_dice[NPLANE];
    __shared__ float s_mm[NPLANE];
    __shared__ int s_isLast;

    const int lane = threadIdx.x & 31;
    const int gw = blockIdx.x * WPB + (threadIdx.x >> 5);
    const int cg    = gw & 1;                    // column group 0..1 (256 cols)
    const int strip = (gw >> 1) & (NSTRIPS - 1); // 0..31
    const int plane = gw >> 6;                   // 0..31
    const int c0 = cg * 256 + lane * 8;
    const bool lE = (cg > 0);
    const bool rE = (cg < 1);
    const int row0 = strip * RPW;

    const float* lg = logits  + (size_t)plane * HH * WW;
    const float* tg = targets + (size_t)plane * HH * WW;

    // ---- L2 prefetch prologue: get rows row0-1 .. row0+PD streaming in ----
    #pragma unroll
    for (int j = -1; j <= PD; j++) {
        int pr = clampr(row0 + j);
        pf_l2(lg + (size_t)pr * WW + c0);
        pf_l2(tg + (size_t)pr * WW + c0);
    }

    float s_pt = 0.f, s_p = 0.f;
    int s_ti = 0, s_mi = 0;

    // ---- software-pipelined rolling stencil: one raw row always in flight ----
    Raw rA = ld_raw(lg, tg, clampr(row0 - 1), c0, lane, lE, rE);  // top halo
    Raw rB = ld_raw(lg, tg, row0, c0, lane, lE, rE);
    Row h0 = proc_halo(rA, row0 - 1, lane, lE, rE);
    Raw rC = ld_raw(lg, tg, row0 + 1, c0, lane, lE, rE);
    Row h1 = proc<true>(rB, lane, lE, rE, s_pt, s_p, s_ti);

    #pragma unroll
    for (int k = 0; k < RPW - 1; k++) {
        // stream L2 prefetch PD rows ahead of the consume point
        {
            int pr = clampr(row0 + k + 2 + PD);
            pf_l2(lg + (size_t)pr * WW + c0);
            pf_l2(tg + (size_t)pr * WW + c0);
        }
        // prefetch row row0+k+2 into registers (clamped: last iter = halo row)
        Raw rN = ld_raw(lg, tg, clampr(row0 + k + 2), c0, lane, lE, rE);
        Row h2 = proc<true>(rC, lane, lE, rE, s_pt, s_p, s_ti);
        s_mi += combine(h0, h1, h2);
        h0 = h1; h1 = h2; rC = rN;
    }
    {   // bottom halo row (raw already prefetched into rC)
        Row h2 = proc_halo(rC, row0 + RPW, lane, lE, rE);
        s_mi += combine(h0, h1, h2);
    }

    // ---- warp reduce ----
    float s_t = (float)s_ti, s_m = (float)s_mi;
    #pragma unroll
    for (int o = 16; o > 0; o >>= 1) {
        s_pt += __shfl_down_sync(0xffffffffu, s_pt, o);
        s_p  += __shfl_down_sync(0xffffffffu, s_p,  o);
        s_t  += __shfl_down_sync(0xffffffffu, s_t,  o);
        s_m  += __shfl_down_sync(0xffffffffu, s_m,  o);
    }
    int w = threadIdx.x >> 5;
    if (lane == 0) {
        red[w][0] = s_pt; red[w][1] = s_p; red[w][2] = s_t; red[w][3] = s_m;
    }
    __syncthreads();
    if (threadIdx.x == 0) {
        float a = 0.f, b = 0.f, c2 = 0.f, d = 0.f;
        #pragma unroll
        for (int j = 0; j < WPB; j++) {
            a += red[j][0]; b += red[j][1]; c2 += red[j][2]; d += red[j][3];
        }
        g_part[blockIdx.x] = make_float4(a, b, c2, d);   // plane = blockIdx.x >> 3
        __threadfence();
        int v = atomicAdd(&g_ctr, 1);
        s_isLast = (v == NBLK - 1);
    }
    __syncthreads();

    // ---- final reduction in last block ----
    if (s_isLast) {
        __threadfence();
        int tid = threadIdx.x;
        if (tid < NPLANE) {
            float a = 0.f, b = 0.f, c2 = 0.f, m = 0.f;
            #pragma unroll
            for (int s = 0; s < NBLK / NPLANE; s++) {
                float4 v = g_part[tid * (NBLK / NPLANE) + s];
                a += v.x; b += v.y; c2 += v.z; m += v.w;
            }
            s_dice[tid] = (2.0f * a + 1.0f) / (b + c2 + 1.0f);  // SMOOTH=1
            s_mm[tid] = m;
        }
        __syncthreads();
        if (tid == 0) {
            float mt = 0.0f;
            #pragma unroll
            for (int j = 0; j < NPLANE; j++) mt += s_mm[j];

            float wsum = 0.0f, dl = 0.0f;
            #pragma unroll
            for (int c = 0; c < CC; c++) {
                float acc = 0.0f;
                #pragma unroll
                for (int b = 0; b < BB; b++) acc += s_dice[b * CC + c];
                dl += cw[c] * (1.0f - acc / (float)BB);
                wsum += cw[c];
            }
            dl /= wsum;
            float bl = 100.0f * mt / (float)((long long)BB * CC * HH * WW);
            out[0] = 0.7f * dl + 0.3f * bl;
            g_ctr = 0;   // reset for next graph replay
        }
    }
}

extern "C" void kernel_launch(void* const* d_in, const int* in_sizes, int n_in,
                              void* d_out, int out_size)
{
    const float* logits  = (const float*)d_in[0];
    const float* targets = (const float*)d_in[1];
    const float* cw      = (const float*)d_in[2];

    loss_fused<<<NBLK, NT>>>(logits, targets, cw, (float*)d_out);
}

// round 15
// speedup vs baseline: 1.1257x; 1.1257x over previous
#include <cuda_runtime.h>

#define BB 8
#define CC 4
#define HH 512
#define WW 512
#define RPW 16                         // rows per warp strip
#define NSTRIPS (HH / RPW)             // 32
#define NPLANE (BB * CC)               // 32
#define NT 256
#define WPB (NT / 32)                  // 8 warps/block
#define NBLK (NPLANE * NSTRIPS * 2 / WPB)   // 256 (2 column groups of 256)

#define NEG4F 0xC0800000u              // -4.0f bit pattern (u-domain padded s)

__device__ float4 g_part[NBLK];
__device__ int g_ctr = 0;

// u = tanh(x/2); p = sigmoid(x) = 0.5u + 0.5. All Sobel math in u-domain.
__device__ __forceinline__ float uhalf(float x) {
    float t;
    asm("tanh.approx.f32 %0, %1;" : "=f"(t) : "f"(0.5f * x));
    return t;
}
__device__ __forceinline__ unsigned prmt(unsigned a, unsigned b, unsigned s) {
    unsigned r;
    asm("prmt.b32 %0, %1, %2, %3;" : "=r"(r) : "r"(a), "r"(b), "r"(s));
    return r;
}
__device__ __forceinline__ float fsel(float v, float w, unsigned m) {
    // m ? v : w, bitwise
    return __uint_as_float((__float_as_uint(v) & m) | (__float_as_uint(w) & ~m));
}
__device__ __forceinline__ float fand(float v, unsigned m) {
    return __uint_as_float(__float_as_uint(v) & m);
}

struct Row {
    float s[8], d[8];             // horizontal sobel partials (u-domain)
    unsigned sb0, sb1, db0, db1;  // packed-byte partials (targets)
};

// Unguarded fetch: row gr MUST be in [0, HH).
template <bool DICE>
__device__ __forceinline__ Row fetch(const float* __restrict__ lg,
                                     const float* __restrict__ tg,
                                     int gr, int c0, int lane,
                                     bool lE, bool rE,
                                     float& s_ut, float& s_u, int& s_ti)
{
    const float* rowp = lg + (size_t)gr * WW + c0;
    const float* rowt = tg + (size_t)gr * WW + c0;
    float4 xa = __ldg((const float4*)rowp);
    float4 xb = __ldg((const float4*)(rowp + 4));
    float4 ta = __ldg((const float4*)rowt);
    float4 tb = __ldg((const float4*)(rowt + 4));

    float xl = 0.f, xr = 0.f;
    unsigned tl = 0u, tr = 0u;
    if (lane == 0 && lE) {
        xl = __ldg(rowp - 1);
        tl = __float_as_uint(__ldg(rowt - 1)) >> 29;
    }
    if (lane == 31 && rE) {
        xr = __ldg(rowp + 8);
        tr = __float_as_uint(__ldg(rowt + 8)) >> 29;
    }

    float u[8];
    u[0] = uhalf(xa.x); u[1] = uhalf(xa.y); u[2] = uhalf(xa.z); u[3] = uhalf(xa.w);
    u[4] = uhalf(xb.x); u[5] = uhalf(xb.y); u[6] = uhalf(xb.z); u[7] = uhalf(xb.w);
    unsigned q1 = prmt(__float_as_uint(ta.x), __float_as_uint(ta.y), 0x0073u);
    unsigned q2 = prmt(__float_as_uint(ta.z), __float_as_uint(ta.w), 0x7300u);
    unsigned tw0 = (q1 | q2) & 0x01010101u;
    unsigned q3 = prmt(__float_as_uint(tb.x), __float_as_uint(tb.y), 0x0073u);
    unsigned q4 = prmt(__float_as_uint(tb.z), __float_as_uint(tb.w), 0x7300u);
    unsigned tw1 = (q3 | q4) & 0x01010101u;

    if (DICE) {
        s_ut = __fmaf_rn(u[0], ta.x, s_ut);
        s_ut = __fmaf_rn(u[1], ta.y, s_ut);
        s_ut = __fmaf_rn(u[2], ta.z, s_ut);
        s_ut = __fmaf_rn(u[3], ta.w, s_ut);
        s_ut = __fmaf_rn(u[4], tb.x, s_ut);
        s_ut = __fmaf_rn(u[5], tb.y, s_ut);
        s_ut = __fmaf_rn(u[6], tb.z, s_ut);
        s_ut = __fmaf_rn(u[7], tb.w, s_ut);
        s_u += ((u[0] + u[1]) + (u[2] + u[3])) + ((u[4] + u[5]) + (u[6] + u[7]));
        s_ti += __popc(tw0) + __popc(tw1);
    }

    float ulin = __shfl_up_sync(0xffffffffu, u[7], 1);
    float urin = __shfl_down_sync(0xffffffffu, u[0], 1);
    unsigned twl = __shfl_up_sync(0xffffffffu, tw1, 1);
    unsigned twr = __shfl_down_sync(0xffffffffu, tw0, 1);
    float ul = ulin, ur = urin;
    unsigned tli = twl >> 24, tri = twr & 0xffu;
    if (lane == 0)  { ul = lE ? uhalf(xl) : -1.f; tli = tl; }   // u-pad = -1
    if (lane == 31) { ur = rE ? uhalf(xr) : -1.f; tri = tr; }

    Row h;
    h.s[0] = __fmaf_rn(2.f, u[0], ul + u[1]); h.d[0] = u[1] - ul;
    #pragma unroll
    for (int i = 1; i < 7; i++) {
        h.s[i] = __fmaf_rn(2.f, u[i], u[i-1] + u[i+1]);
        h.d[i] = u[i+1] - u[i-1];
    }
    h.s[7] = __fmaf_rn(2.f, u[7], u[6] + ur); h.d[7] = ur - u[6];

    unsigned wl0 = (tw0 << 8) | tli;
    unsigned wr0 = (tw0 >> 8) | ((tw1 & 0xffu) << 24);
    h.sb0 = wl0 + 2u * tw0 + wr0;
    h.db0 = (wr0 + 0x02020202u) - wl0;
    unsigned wl1 = (tw1 << 8) | (tw0 >> 24);
    unsigned wr1 = (tw1 >> 8) | (tri << 24);
    h.sb1 = wl1 + 2u * tw1 + wr1;
    h.db1 = (wr1 + 0x02020202u) - wl1;
    return h;
}

// Halo fetch: row may be out of range. A fully-padded probs row has u = -1
// everywhere => s = -4, d = 0. Target padded row: sb = 0, db biased zero.
__device__ __forceinline__ Row fetch_halo(const float* __restrict__ lg,
                                          const float* __restrict__ tg,
                                          int gr, int c0, int lane,
                                          bool lE, bool rE)
{
    const unsigned msk = ((unsigned)gr < (unsigned)HH) ? 0xffffffffu : 0u;
    const float spad = __uint_as_float(NEG4F);
    int grc = gr < 0 ? 0 : (gr >= HH ? HH - 1 : gr);
    float dut = 0.f, du = 0.f; int dti = 0;
    Row h = fetch<false>(lg, tg, grc, c0, lane, lE, rE, dut, du, dti);
    #pragma unroll
    for (int i = 0; i < 8; i++) {
        h.s[i] = fsel(h.s[i], spad, msk);
        h.d[i] = fand(h.d[i], msk);
    }
    h.sb0 &= msk; h.sb1 &= msk;
    h.db0 = (h.db0 & msk) | (0x02020202u & ~msk);
    h.db1 = (h.db1 & msk) | (0x02020202u & ~msk);
    return h;
}

__device__ __forceinline__ int combine(const Row& h0, const Row& h1, const Row& h2)
{
    bool pb[8];
    #pragma unroll
    for (int i = 0; i < 8; i++) {
        float gx = __fmaf_rn(2.f, h1.d[i], h0.d[i] + h2.d[i]);
        float gy = h2.s[i] - h0.s[i];
        // u-domain: true mag^2 = 0.25*(gx^2+gy^2); (mag > 0.5) <=> (... > 1)
        pb[i] = __fmaf_rn(gx, gx, gy * gy) > 1.0f;
    }
    unsigned hx0 = h0.db0 + 2u * h1.db0 + h2.db0;
    unsigned hy0 = (h2.sb0 + 0x04040404u) - h0.sb0;
    unsigned cmb0 = (hx0 ^ 0x08080808u) | (hy0 ^ 0x04040404u);
    unsigned hx1 = h0.db1 + 2u * h1.db1 + h2.db1;
    unsigned hy1 = (h2.sb1 + 0x04040404u) - h0.sb1;
    unsigned cmb1 = (hx1 ^ 0x08080808u) | (hy1 ^ 0x04040404u);

    int m = 0;
    m += (int)(pb[0] != ((cmb0 & 0x000000FFu) != 0));
    m += (int)(pb[1] != ((cmb0 & 0x0000FF00u) != 0));
    m += (int)(pb[2] != ((cmb0 & 0x00FF0000u) != 0));
    m += (int)(pb[3] != ((cmb0 >> 24) != 0));
    m += (int)(pb[4] != ((cmb1 & 0x000000FFu) != 0));
    m += (int)(pb[5] != ((cmb1 & 0x0000FF00u) != 0));
    m += (int)(pb[6] != ((cmb1 & 0x00FF0000u) != 0));
    m += (int)(pb[7] != ((cmb1 >> 24) != 0));
    return m;
}

__global__ __launch_bounds__(NT, 2) void loss_fused(
    const float* __restrict__ logits, const float* __restrict__ targets,
    const float* __restrict__ cw, float* __restrict__ out)
{
    __shared__ float red[WPB][4];
    __shared__ float s_dice[NPLANE];
    __shared__ float s_mm[NPLANE];
    __shared__ int s_isLast;

    const int lane = threadIdx.x & 31;
    const int gw = blockIdx.x * WPB + (threadIdx.x >> 5);
    const int cg    = gw & 1;                    // column group 0..1 (256 cols)
    const int strip = (gw >> 1) & (NSTRIPS - 1); // 0..31
    const int plane = gw >> 6;                   // 0..31
    const int c0 = cg * 256 + lane * 8;
    const bool lE = (cg > 0);
    const bool rE = (cg < 1);
    const int row0 = strip * RPW;

    const float* lg = logits  + (size_t)plane * HH * WW;
    const float* tg = targets + (size_t)plane * HH * WW;

    float s_ut = 0.f, s_u = 0.f;
    int s_ti = 0, s_mi = 0;

    // prologue: top halo (masked) + first interior row
    Row h0 = fetch_halo(lg, tg, row0 - 1, c0, lane, lE, rE);
    Row h1 = fetch<true>(lg, tg, row0, c0, lane, lE, rE, s_ut, s_u, s_ti);

    // hot loop: rows row0+1 .. row0+RPW-1 always in range — branch-free
    #pragma unroll
    for (int k = 0; k < RPW - 1; k++) {
        Row h2 = fetch<true>(lg, tg, row0 + k + 1, c0, lane, lE, rE,
                             s_ut, s_u, s_ti);
        s_mi += combine(h0, h1, h2);
        h0 = h1; h1 = h2;
    }
    // epilogue: bottom halo (masked)
    {
        Row h2 = fetch_halo(lg, tg, row0 + RPW, c0, lane, lE, rE);
        s_mi += combine(h0, h1, h2);
    }

    // u-domain -> p-domain corrections (per thread; 128 dice px per thread)
    float s_t = (float)s_ti;
    float s_pt = 0.5f * (s_ut + s_t);            // sum p*t
    float s_p  = __fmaf_rn(0.5f, s_u, 64.0f);    // sum p = 0.5*sum u + 0.5*128
    float s_m  = (float)s_mi;

    // ---- warp reduce ----
    #pragma unroll
    for (int o = 16; o > 0; o >>= 1) {
        s_pt += __shfl_down_sync(0xffffffffu, s_pt, o);
        s_p  += __shfl_down_sync(0xffffffffu, s_p,  o);
        s_t  += __shfl_down_sync(0xffffffffu, s_t,  o);
        s_m  += __shfl_down_sync(0xffffffffu, s_m,  o);
    }
    int w = threadIdx.x >> 5;
    if (lane == 0) {
        red[w][0] = s_pt; red[w][1] = s_p; red[w][2] = s_t; red[w][3] = s_m;
    }
    __syncthreads();
    if (threadIdx.x == 0) {
        float a = 0.f, b = 0.f, c2 = 0.f, d = 0.f;
        #pragma unroll
        for (int j = 0; j < WPB; j++) {
            a += red[j][0]; b += red[j][1]; c2 += red[j][2]; d += red[j][3];
        }
        g_part[blockIdx.x] = make_float4(a, b, c2, d);   // plane = blockIdx.x >> 3
        __threadfence();
        int v = atomicAdd(&g_ctr, 1);
        s_isLast = (v == NBLK - 1);
    }
    __syncthreads();

    // ---- final reduction in last block ----
    if (s_isLast) {
        __threadfence();
        int tid = threadIdx.x;
        if (tid < NPLANE) {
            float a = 0.f, b = 0.f, c2 = 0.f, m = 0.f;
            #pragma unroll
            for (int s = 0; s < NBLK / NPLANE; s++) {
                float4 v = g_part[tid * (NBLK / NPLANE) + s];
                a += v.x; b += v.y; c2 += v.z; m += v.w;
            }
            s_dice[tid] = (2.0f * a + 1.0f) / (b + c2 + 1.0f);  // SMOOTH=1
            s_mm[tid] = m;
        }
        __syncthreads();
        if (tid == 0) {
            float mt = 0.0f;
            #pragma unroll
            for (int j = 0; j < NPLANE; j++) mt += s_mm[j];

            float wsum = 0.0f, dl = 0.0f;
            #pragma unroll
            for (int c = 0; c < CC; c++) {
                float acc = 0.0f;
                #pragma unroll
                for (int b = 0; b < BB; b++) acc += s_dice[b * CC + c];
                dl += cw[c] * (1.0f - acc / (float)BB);
                wsum += cw[c];
            }
            dl /= wsum;
            float bl = 100.0f * mt / (float)((long long)BB * CC * HH * WW);
            out[0] = 0.7f * dl + 0.3f * bl;
            g_ctr = 0;   // reset for next graph replay
        }
    }
}

extern "C" void kernel_launch(void* const* d_in, const int* in_sizes, int n_in,
                              void* d_out, int out_size)
{
    const float* logits  = (const float*)d_in[0];
    const float* targets = (const float*)d_in[1];
    const float* cw      = (const float*)d_in[2];

    loss_fused<<<NBLK, NT>>>(logits, targets, cw, (float*)d_out);
}

// round 16
// speedup vs baseline: 1.1385x; 1.0114x over previous
#include <cuda_runtime.h>

#define BB 8
#define CC 4
#define HH 512
#define WW 512
#define RPW 16                         // rows per warp strip
#define NSTRIPS (HH / RPW)             // 32
#define NPLANE (BB * CC)               // 32
#define NT 256
#define WPB (NT / 32)                  // 8 warps/block
#define NBLK (NPLANE * NSTRIPS * 2 / WPB)   // 256 (2 column groups of 256)

#define NEG4F 0xC0800000u              // -4.0f bits (u-domain padded s)

__device__ float4 g_part[NBLK];
__device__ int g_ctr = 0;

// u = tanh(x/2); p = sigmoid(x) = 0.5u + 0.5. All Sobel math in u-domain.
__device__ __forceinline__ float uhalf(float x) {
    float t;
    asm("tanh.approx.f32 %0, %1;" : "=f"(t) : "f"(0.5f * x));
    return t;
}
__device__ __forceinline__ unsigned prmt(unsigned a, unsigned b, unsigned s) {
    unsigned r;
    asm("prmt.b32 %0, %1, %2, %3;" : "=r"(r) : "r"(a), "r"(b), "r"(s));
    return r;
}
__device__ __forceinline__ float fsel(float v, float w, unsigned m) {
    return __uint_as_float((__float_as_uint(v) & m) | (__float_as_uint(w) & ~m));
}
__device__ __forceinline__ float fand(float v, unsigned m) {
    return __uint_as_float(__float_as_uint(v) & m);
}

struct Row {
    float s[8], d[8];             // horizontal sobel partials (u-domain)
    unsigned sb0, sb1, db0, db1;  // packed-byte partials (targets)
};

// Unguarded, BRANCH-FREE fetch: row gr MUST be in [0, HH).
// offE: per-lane edge-load offset (lane0: lE?-1:0, lane31: rE?8:0, else 0).
template <bool DICE>
__device__ __forceinline__ Row fetch(const float* __restrict__ lg,
                                     const float* __restrict__ tg,
                                     int gr, int c0, int lane, int offE,
                                     bool lE, bool rE,
                                     float& s_ut, float& s_u, int& s_ti)
{
    const float* rowp = lg + (size_t)gr * WW + c0;
    const float* rowt = tg + (size_t)gr * WW + c0;
    float4 xa = __ldg((const float4*)rowp);
    float4 xb = __ldg((const float4*)(rowp + 4));
    float4 ta = __ldg((const float4*)rowt);
    float4 tb = __ldg((const float4*)(rowt + 4));
    // unconditional edge loads (dummy offset 0 for interior lanes)
    float xe = __ldg(rowp + offE);
    float te = __ldg(rowt + offE);

    float u[8];
    u[0] = uhalf(xa.x); u[1] = uhalf(xa.y); u[2] = uhalf(xa.z); u[3] = uhalf(xa.w);
    u[4] = uhalf(xb.x); u[5] = uhalf(xb.y); u[6] = uhalf(xb.z); u[7] = uhalf(xb.w);
    unsigned q1 = prmt(__float_as_uint(ta.x), __float_as_uint(ta.y), 0x0073u);
    unsigned q2 = prmt(__float_as_uint(ta.z), __float_as_uint(ta.w), 0x7300u);
    unsigned tw0 = (q1 | q2) & 0x01010101u;
    unsigned q3 = prmt(__float_as_uint(tb.x), __float_as_uint(tb.y), 0x0073u);
    unsigned q4 = prmt(__float_as_uint(tb.z), __float_as_uint(tb.w), 0x7300u);
    unsigned tw1 = (q3 | q4) & 0x01010101u;

    if (DICE) {
        s_ut = __fmaf_rn(u[0], ta.x, s_ut);
        s_ut = __fmaf_rn(u[1], ta.y, s_ut);
        s_ut = __fmaf_rn(u[2], ta.z, s_ut);
        s_ut = __fmaf_rn(u[3], ta.w, s_ut);
        s_ut = __fmaf_rn(u[4], tb.x, s_ut);
        s_ut = __fmaf_rn(u[5], tb.y, s_ut);
        s_ut = __fmaf_rn(u[6], tb.z, s_ut);
        s_ut = __fmaf_rn(u[7], tb.w, s_ut);
        s_u += ((u[0] + u[1]) + (u[2] + u[3])) + ((u[4] + u[5]) + (u[6] + u[7]));
        s_ti += __popc(tw0) + __popc(tw1);
    }

    // packed neighbor exchange: u value (LSB zeroed) | target bit
    unsigned pk7 = (__float_as_uint(u[7]) & ~1u) | (tw1 >> 24);
    unsigned pk0 = (__float_as_uint(u[0]) & ~1u) | (tw0 & 1u);
    unsigned rl = __shfl_up_sync(0xffffffffu, pk7, 1);
    unsigned rr = __shfl_down_sync(0xffffffffu, pk0, 1);
    float ul = __uint_as_float(rl & ~1u);
    float ur = __uint_as_float(rr & ~1u);
    unsigned tli = rl & 1u, tri = rr & 1u;

    // edge-lane fixups: warp-uniform SELs, no divergence
    float ue = uhalf(xe);
    unsigned teb = __float_as_uint(te) >> 29;
    if (lane == 0)  { ul = lE ? ue : -1.f; tli = lE ? teb : 0u; }
    if (lane == 31) { ur = rE ? ue : -1.f; tri = rE ? teb : 0u; }

    Row h;
    h.s[0] = __fmaf_rn(2.f, u[0], ul + u[1]); h.d[0] = u[1] - ul;
    #pragma unroll
    for (int i = 1; i < 7; i++) {
        h.s[i] = __fmaf_rn(2.f, u[i], u[i-1] + u[i+1]);
        h.d[i] = u[i+1] - u[i-1];
    }
    h.s[7] = __fmaf_rn(2.f, u[7], u[6] + ur); h.d[7] = ur - u[6];

    unsigned wl0 = (tw0 << 8) | tli;
    unsigned wr0 = (tw0 >> 8) | ((tw1 & 0xffu) << 24);
    h.sb0 = wl0 + 2u * tw0 + wr0;
    h.db0 = (wr0 + 0x02020202u) - wl0;
    unsigned wl1 = (tw1 << 8) | (tw0 >> 24);
    unsigned wr1 = (tw1 >> 8) | (tri << 24);
    h.sb1 = wl1 + 2u * tw1 + wr1;
    h.db1 = (wr1 + 0x02020202u) - wl1;
    return h;
}

// Halo fetch: row may be out of range. Padded probs row: u=-1 => s=-4, d=0.
// Padded target row: sb=0, db biased zero.
__device__ __forceinline__ Row fetch_halo(const float* __restrict__ lg,
                                          const float* __restrict__ tg,
                                          int gr, int c0, int lane, int offE,
                                          bool lE, bool rE)
{
    const unsigned msk = ((unsigned)gr < (unsigned)HH) ? 0xffffffffu : 0u;
    const float spad = __uint_as_float(NEG4F);
    int grc = gr < 0 ? 0 : (gr >= HH ? HH - 1 : gr);
    float dut = 0.f, du = 0.f; int dti = 0;
    Row h = fetch<false>(lg, tg, grc, c0, lane, offE, lE, rE, dut, du, dti);
    #pragma unroll
    for (int i = 0; i < 8; i++) {
        h.s[i] = fsel(h.s[i], spad, msk);
        h.d[i] = fand(h.d[i], msk);
    }
    h.sb0 &= msk; h.sb1 &= msk;
    h.db0 = (h.db0 & msk) | (0x02020202u & ~msk);
    h.db1 = (h.db1 & msk) | (0x02020202u & ~msk);
    return h;
}

__device__ __forceinline__ int combine(const Row& h0, const Row& h1, const Row& h2)
{
    bool pb[8];
    #pragma unroll
    for (int i = 0; i < 8; i++) {
        float gx = __fmaf_rn(2.f, h1.d[i], h0.d[i] + h2.d[i]);
        float gy = h2.s[i] - h0.s[i];
        // u-domain: true mag^2 = 0.25*(gx^2+gy^2); (mag > 0.5) <=> (... > 1)
        pb[i] = __fmaf_rn(gx, gx, gy * gy) > 1.0f;
    }
    unsigned hx0 = h0.db0 + 2u * h1.db0 + h2.db0;
    unsigned hy0 = (h2.sb0 + 0x04040404u) - h0.sb0;
    unsigned cmb0 = (hx0 ^ 0x08080808u) | (hy0 ^ 0x04040404u);
    unsigned hx1 = h0.db1 + 2u * h1.db1 + h2.db1;
    unsigned hy1 = (h2.sb1 + 0x04040404u) - h0.sb1;
    unsigned cmb1 = (hx1 ^ 0x08080808u) | (hy1 ^ 0x04040404u);

    int m = 0;
    m += (int)(pb[0] != ((cmb0 & 0x000000FFu) != 0));
    m += (int)(pb[1] != ((cmb0 & 0x0000FF00u) != 0));
    m += (int)(pb[2] != ((cmb0 & 0x00FF0000u) != 0));
    m += (int)(pb[3] != ((cmb0 >> 24) != 0));
    m += (int)(pb[4] != ((cmb1 & 0x000000FFu) != 0));
    m += (int)(pb[5] != ((cmb1 & 0x0000FF00u) != 0));
    m += (int)(pb[6] != ((cmb1 & 0x00FF0000u) != 0));
    m += (int)(pb[7] != ((cmb1 >> 24) != 0));
    return m;
}

__global__ __launch_bounds__(NT, 2) void loss_fused(
    const float* __restrict__ logits, const float* __restrict__ targets,
    const float* __restrict__ cw, float* __restrict__ out)
{
    __shared__ float red[WPB][4];
    __shared__ float s_dice[NPLANE];
    __shared__ float s_mm[NPLANE];
    __shared__ int s_isLast;

    const int lane = threadIdx.x & 31;
    const int gw = blockIdx.x * WPB + (threadIdx.x >> 5);
    const int cg    = gw & 1;                    // column group 0..1 (256 cols)
    const int strip = (gw >> 1) & (NSTRIPS - 1); // 0..31
    const int plane = gw >> 6;                   // 0..31
    const int c0 = cg * 256 + lane * 8;
    const bool lE = (cg > 0);
    const bool rE = (cg < 1);
    const int row0 = strip * RPW;

    // per-lane branch-free edge-load offset (in-range dummy 0 for interior)
    int offE = 0;
    if (lane == 0)  offE = lE ? -1 : 0;
    if (lane == 31) offE = rE ? 8 : 0;

    const float* lg = logits  + (size_t)plane * HH * WW;
    const float* tg = targets + (size_t)plane * HH * WW;

    float s_ut = 0.f, s_u = 0.f;
    int s_ti = 0, s_mi = 0;

    // prologue: top halo (masked) + first interior row
    Row h0 = fetch_halo(lg, tg, row0 - 1, c0, lane, offE, lE, rE);
    Row h1 = fetch<true>(lg, tg, row0, c0, lane, offE, lE, rE, s_ut, s_u, s_ti);

    // hot loop: rows row0+1 .. row0+RPW-1 always in range — branch-free
    #pragma unroll
    for (int k = 0; k < RPW - 1; k++) {
        Row h2 = fetch<true>(lg, tg, row0 + k + 1, c0, lane, offE, lE, rE,
                             s_ut, s_u, s_ti);
        s_mi += combine(h0, h1, h2);
        h0 = h1; h1 = h2;
    }
    // epilogue: bottom halo (masked)
    {
        Row h2 = fetch_halo(lg, tg, row0 + RPW, c0, lane, offE, lE, rE);
        s_mi += combine(h0, h1, h2);
    }

    // u-domain -> p-domain corrections (128 dice px per thread)
    float s_t = (float)s_ti;
    float s_pt = 0.5f * (s_ut + s_t);            // sum p*t
    float s_p  = __fmaf_rn(0.5f, s_u, 64.0f);    // sum p = 0.5*sum u + 0.5*128
    float s_m  = (float)s_mi;

    // ---- warp reduce ----
    #pragma unroll
    for (int o = 16; o > 0; o >>= 1) {
        s_pt += __shfl_down_sync(0xffffffffu, s_pt, o);
        s_p  += __shfl_down_sync(0xffffffffu, s_p,  o);
        s_t  += __shfl_down_sync(0xffffffffu, s_t,  o);
        s_m  += __shfl_down_sync(0xffffffffu, s_m,  o);
    }
    int w = threadIdx.x >> 5;
    if (lane == 0) {
        red[w][0] = s_pt; red[w][1] = s_p; red[w][2] = s_t; red[w][3] = s_m;
    }
    __syncthreads();
    if (threadIdx.x == 0) {
        float a = 0.f, b = 0.f, c2 = 0.f, d = 0.f;
        #pragma unroll
        for (int j = 0; j < WPB; j++) {
            a += red[j][0]; b += red[j][1]; c2 += red[j][2]; d += red[j][3];
        }
        g_part[blockIdx.x] = make_float4(a, b, c2, d);
        __threadfence();
        int v = atomicAdd(&g_ctr, 1);
        s_isLast = (v == NBLK - 1);
    }
    __syncthreads();

    // ---- final reduction in last block ----
    if (s_isLast) {
        __threadfence();
        int tid = threadIdx.x;
        if (tid < NPLANE) {
            float a = 0.f, b = 0.f, c2 = 0.f, m = 0.f;
            #pragma unroll
            for (int s = 0; s < NBLK / NPLANE; s++) {
                float4 v = g_part[tid * (NBLK / NPLANE) + s];
                a += v.x; b += v.y; c2 += v.z; m += v.w;
            }
            s_dice[tid] = (2.0f * a + 1.0f) / (b + c2 + 1.0f);  // SMOOTH=1
            s_mm[tid] = m;
        }
        __syncthreads();
        if (tid == 0) {
            float mt = 0.0f;
            #pragma unroll
            for (int j = 0; j < NPLANE; j++) mt += s_mm[j];

            float wsum = 0.0f, dl = 0.0f;
            #pragma unroll
            for (int c = 0; c < CC; c++) {
                float acc = 0.0f;
                #pragma unroll
                for (int b = 0; b < BB; b++) acc += s_dice[b * CC + c];
                dl += cw[c] * (1.0f - acc / (float)BB);
                wsum += cw[c];
            }
            dl /= wsum;
            float bl = 100.0f * mt / (float)((long long)BB * CC * HH * WW);
            out[0] = 0.7f * dl + 0.3f * bl;
            g_ctr = 0;   // reset for next graph replay
        }
    }
}

extern "C" void kernel_launch(void* const* d_in, const int* in_sizes, int n_in,
                              void* d_out, int out_size)
{
    const float* logits  = (const float*)d_in[0];
    const float* targets = (const float*)d_in[1];
    const float* cw      = (const float*)d_in[2];

    loss_fused<<<NBLK, NT>>>(logits, targets, cw, (float*)d_out);
}